// round 1
// baseline (speedup 1.0000x reference)
#include <cuda_runtime.h>

#define NN 100000
#define EE 1600000
#define FD 128
#define GG 512
#define LL 3
#define TG 64
#define NB ((NN + 1023) / 1024)   /* 98 scan blocks */

// ---------------- device scratch (no allocs allowed) ----------------
__device__ float g_h[(size_t)NN * FD];
__device__ float g_aggr[(size_t)NN * FD];
__device__ float g_t[(size_t)NN * FD];
__device__ int   g_deg[NN];
__device__ int   g_rowptr[NN + 1];
__device__ int   g_cursor[NN];
__device__ int   g_bsum[NB];
__device__ int   g_boff[NB];
__device__ int   g_srcsorted[EE];
__device__ int   g_gstart[GG + 1];

// ---------------- CSR build ----------------
__global__ void k_zero_deg() {
    int i = blockIdx.x * 256 + threadIdx.x;
    if (i < NN) g_deg[i] = 0;
}

__global__ void k_hist(const int* __restrict__ dst) {
    int e = blockIdx.x * 256 + threadIdx.x;
    if (e < EE) atomicAdd(&g_deg[dst[e]], 1);
}

__global__ void k_scan1() {
    __shared__ int sh[1024];
    int i = blockIdx.x * 1024 + threadIdx.x;
    int v = (i < NN) ? g_deg[i] : 0;
    sh[threadIdx.x] = v;
    __syncthreads();
    for (int off = 1; off < 1024; off <<= 1) {
        int t = sh[threadIdx.x];
        int a = (threadIdx.x >= off) ? sh[threadIdx.x - off] : 0;
        __syncthreads();
        sh[threadIdx.x] = t + a;
        __syncthreads();
    }
    if (i < NN) g_rowptr[i + 1] = sh[threadIdx.x];
    if (threadIdx.x == 1023) g_bsum[blockIdx.x] = sh[1023];
}

__global__ void k_scan2() {
    __shared__ int sh[128];
    int t = threadIdx.x;
    int v = (t < NB) ? g_bsum[t] : 0;
    sh[t] = v;
    __syncthreads();
    for (int off = 1; off < 128; off <<= 1) {
        int x = sh[t];
        int a = (t >= off) ? sh[t - off] : 0;
        __syncthreads();
        sh[t] = x + a;
        __syncthreads();
    }
    if (t < NB) g_boff[t] = sh[t] - v;   // exclusive block offsets
}

__global__ void k_scan3() {
    int i = blockIdx.x * 1024 + threadIdx.x;
    if (i < NN) g_rowptr[i + 1] += g_boff[blockIdx.x];
    if (i == 0) g_rowptr[0] = 0;
}

__global__ void k_copycur() {
    int i = blockIdx.x * 256 + threadIdx.x;
    if (i < NN) g_cursor[i] = g_rowptr[i];
}

__global__ void k_bucket(const int* __restrict__ src, const int* __restrict__ dst) {
    int e = blockIdx.x * 256 + threadIdx.x;
    if (e < EE) {
        int d = dst[e];
        int pos = atomicAdd(&g_cursor[d], 1);
        g_srcsorted[pos] = src[e];
    }
}

__global__ void k_gstart(const int* __restrict__ batch) {
    int g = blockIdx.x * 256 + threadIdx.x;
    if (g <= GG) {
        int lo = 0, hi = NN;  // lower_bound(batch, g); batch < GG always -> gstart[GG]=NN
        while (lo < hi) {
            int mid = (lo + hi) >> 1;
            if (batch[mid] < g) lo = mid + 1; else hi = mid;
        }
        g_gstart[g] = lo;
    }
}

// ---------------- aggregation: warp-per-node gather-sum, no float atomics ----------------
__global__ void __launch_bounds__(256) k_aggr(const float* __restrict__ h) {
    int node = blockIdx.x * 8 + (threadIdx.x >> 5);
    if (node >= NN) return;
    int lane = threadIdx.x & 31;
    int s = g_rowptr[node], e = g_rowptr[node + 1];
    const float4* hp = (const float4*)h;
    float4 acc = make_float4(0.f, 0.f, 0.f, 0.f);
    int i = s;
    for (; i + 1 < e; i += 2) {
        int s0 = g_srcsorted[i], s1 = g_srcsorted[i + 1];
        float4 v0 = hp[(size_t)s0 * 32 + lane];
        float4 v1 = hp[(size_t)s1 * 32 + lane];
        acc.x += v0.x + v1.x; acc.y += v0.y + v1.y;
        acc.z += v0.z + v1.z; acc.w += v0.w + v1.w;
    }
    if (i < e) {
        int s0 = g_srcsorted[i];
        float4 v0 = hp[(size_t)s0 * 32 + lane];
        acc.x += v0.x; acc.y += v0.y; acc.z += v0.z; acc.w += v0.w;
    }
    ((float4*)g_aggr)[(size_t)node * 32 + lane] = acc;
}

// ---------------- fp32 SGEMM: C[M,128] = act( pre(A) @ W[128,128] + bias ) ----------------
// pre(A) = (1+eps)*A + A1 when A1 != null (GIN combine fused into A load)
__global__ void __launch_bounds__(256) k_gemm(
    const float* __restrict__ A, const float* __restrict__ A1,
    const float* __restrict__ epsp,
    const float* __restrict__ W, const float* __restrict__ bias,
    float* __restrict__ C, int M, int relu)
{
    __shared__ float As[16][130];   // [k][m], padded for conflict-free transpose store
    __shared__ float Ws[16][128];   // [k][n]
    int tx = threadIdx.x & 15;      // n-tile
    int ty = threadIdx.x >> 4;      // m-tile
    int m0 = blockIdx.x * 128;
    float alpha = 1.0f;
    if (epsp) alpha = 1.0f + epsp[0];

    float c[8][8];
#pragma unroll
    for (int i = 0; i < 8; i++)
#pragma unroll
        for (int j = 0; j < 8; j++) c[i][j] = 0.f;

    for (int k0 = 0; k0 < 128; k0 += 16) {
        __syncthreads();
#pragma unroll
        for (int it = 0; it < 2; it++) {
            int idx = threadIdx.x + it * 256;       // 0..511
            // A tile: 128 rows x 16 k, transposed store
            int row = idx >> 2;
            int kq = (idx & 3) << 2;
            int m = m0 + row;
            float4 v = make_float4(0.f, 0.f, 0.f, 0.f);
            if (m < M) {
                v = *(const float4*)&A[(size_t)m * FD + k0 + kq];
                if (A1) {
                    float4 w = *(const float4*)&A1[(size_t)m * FD + k0 + kq];
                    v.x = alpha * v.x + w.x; v.y = alpha * v.y + w.y;
                    v.z = alpha * v.z + w.z; v.w = alpha * v.w + w.w;
                }
            }
            As[kq + 0][row] = v.x; As[kq + 1][row] = v.y;
            As[kq + 2][row] = v.z; As[kq + 3][row] = v.w;
            // W tile: 16 k x 128 n
            int kk = idx >> 5;
            int n4 = (idx & 31) << 2;
            *(float4*)&Ws[kk][n4] = *(const float4*)&W[(size_t)(k0 + kk) * FD + n4];
        }
        __syncthreads();
#pragma unroll
        for (int kk = 0; kk < 16; kk++) {
            float a[8];
#pragma unroll
            for (int i = 0; i < 8; i++) a[i] = As[kk][ty * 8 + i];
            float4 b0 = *(const float4*)&Ws[kk][tx * 8];
            float4 b1 = *(const float4*)&Ws[kk][tx * 8 + 4];
            float b[8] = {b0.x, b0.y, b0.z, b0.w, b1.x, b1.y, b1.z, b1.w};
#pragma unroll
            for (int i = 0; i < 8; i++)
#pragma unroll
                for (int j = 0; j < 8; j++) c[i][j] += a[i] * b[j];
        }
    }

    float bb[8];
#pragma unroll
    for (int j = 0; j < 8; j++) bb[j] = bias[tx * 8 + j];
#pragma unroll
    for (int i = 0; i < 8; i++) {
        int m = m0 + ty * 8 + i;
        if (m < M) {
            float o[8];
#pragma unroll
            for (int j = 0; j < 8; j++) {
                float v = c[i][j] + bb[j];
                o[j] = relu ? fmaxf(v, 0.f) : v;
            }
            *(float4*)&C[(size_t)m * FD + tx * 8]     = make_float4(o[0], o[1], o[2], o[3]);
            *(float4*)&C[(size_t)m * FD + tx * 8 + 4] = make_float4(o[4], o[5], o[6], o[7]);
        }
    }
}

// ---------------- GraphNorm (+relu) in place; block per graph, thread per feature ----------------
__global__ void __launch_bounds__(128) k_gnorm(
    float* __restrict__ h,
    const float* __restrict__ scale, const float* __restrict__ weight,
    const float* __restrict__ bias)
{
    int g = blockIdx.x;
    int f = threadIdx.x;
    int s = g_gstart[g], e = g_gstart[g + 1];
    float cnt = fmaxf((float)(e - s), 1.0f);

    float sum = 0.f;
#pragma unroll 4
    for (int i = s; i < e; i++) sum += h[(size_t)i * FD + f];
    float ms = (sum / cnt) * scale[f];

    float v = 0.f;
#pragma unroll 4
    for (int i = s; i < e; i++) {
        float d = h[(size_t)i * FD + f] - ms;
        v += d * d;
    }
    float inv = weight[f] * rsqrtf(v / cnt + 1e-8f);
    float bf = bias[f];

#pragma unroll 4
    for (int i = s; i < e; i++) {
        float d = h[(size_t)i * FD + f] - ms;
        h[(size_t)i * FD + f] = fmaxf(inv * d + bf, 0.f);
    }
}

// ---------------- pool + fused tiny GEMM: out[g, lofs + j] ----------------
__global__ void __launch_bounds__(128) k_pool(
    const float* __restrict__ t,
    const float* __restrict__ w2,   // [128,64] row-major
    const float* __restrict__ b2,   // [64]
    float* __restrict__ out, int lofs)
{
    __shared__ float sp[128];
    int g = blockIdx.x;
    int f = threadIdx.x;
    int s = g_gstart[g], e = g_gstart[g + 1];
    float acc = 0.f;
#pragma unroll 4
    for (int i = s; i < e; i++) acc += t[(size_t)i * FD + f];
    sp[f] = acc;
    __syncthreads();
    if (f < TG) {
        float o = (float)(e - s) * b2[f];   // unclamped count: matches ref for empty graphs
#pragma unroll 8
        for (int k = 0; k < FD; k++) o += sp[k] * w2[k * TG + f];
        out[(size_t)g * (LL * TG) + lofs + f] = o;
    }
}

// ---------------- launcher ----------------
extern "C" void kernel_launch(void* const* d_in, const int* in_sizes, int n_in,
                              void* d_out, int out_size) {
    const float* x        = (const float*)d_in[0];
    const int*   edge     = (const int*)d_in[1];
    const int*   batch    = (const int*)d_in[2];
    const float* conv_w1  = (const float*)d_in[3];
    const float* conv_b1  = (const float*)d_in[4];
    const float* conv_w2  = (const float*)d_in[5];
    const float* conv_b2  = (const float*)d_in[6];
    const float* eps      = (const float*)d_in[7];
    const float* gn_scale = (const float*)d_in[8];
    const float* gn_weight= (const float*)d_in[9];
    const float* gn_bias  = (const float*)d_in[10];
    const float* proj_w1  = (const float*)d_in[11];
    const float* proj_b1  = (const float*)d_in[12];
    const float* proj_w2  = (const float*)d_in[13];
    const float* proj_b2  = (const float*)d_in[14];
    float* out = (float*)d_out;

    const int* src = edge;
    const int* dst = edge + EE;

    float *p_h, *p_aggr, *p_t;
    cudaGetSymbolAddress((void**)&p_h, g_h);
    cudaGetSymbolAddress((void**)&p_aggr, g_aggr);
    cudaGetSymbolAddress((void**)&p_t, g_t);

    // CSR build (dst-sorted edge sources)
    k_zero_deg<<<(NN + 255) / 256, 256>>>();
    k_hist<<<(EE + 255) / 256, 256>>>(dst);
    k_scan1<<<NB, 1024>>>();
    k_scan2<<<1, 128>>>();
    k_scan3<<<NB, 1024>>>();
    k_copycur<<<(NN + 255) / 256, 256>>>();
    k_bucket<<<(EE + 255) / 256, 256>>>(src, dst);
    k_gstart<<<3, 256>>>(batch);

    int gemm_blocks = (NN + 127) / 128;
    const float* h = x;
    for (int l = 0; l < LL; l++) {
        k_aggr<<<(NN + 7) / 8, 256>>>(h);
        // t = relu(((1+eps)h + aggr) @ conv_w1 + b1)
        k_gemm<<<gemm_blocks, 256>>>(h, p_aggr, eps + l,
                                     conv_w1 + (size_t)l * FD * FD,
                                     conv_b1 + (size_t)l * FD, p_t, NN, 1);
        // h = t @ conv_w2 + b2
        k_gemm<<<gemm_blocks, 256>>>(p_t, nullptr, nullptr,
                                     conv_w2 + (size_t)l * FD * FD,
                                     conv_b2 + (size_t)l * FD, p_h, NN, 0);
        // GraphNorm + relu (in place)
        k_gnorm<<<GG, 128>>>(p_h, gn_scale + (size_t)l * FD,
                             gn_weight + (size_t)l * FD, gn_bias + (size_t)l * FD);
        // t = relu(h @ proj_w1 + b1)
        k_gemm<<<gemm_blocks, 256>>>(p_h, nullptr, nullptr,
                                     proj_w1 + (size_t)l * FD * FD,
                                     proj_b1 + (size_t)l * FD, p_t, NN, 1);
        // pooled = segsum(t); out_l = pooled @ proj_w2 + count*b2
        k_pool<<<GG, 128>>>(p_t, proj_w2 + (size_t)l * FD * TG,
                            proj_b2 + (size_t)l * TG, out, l * TG);
        h = p_h;
    }
}

// round 3
// speedup vs baseline: 1.3511x; 1.3511x over previous
#include <cuda_runtime.h>
#include <cstdint>

#define NN 100000
#define EE 1600000
#define FD 128
#define GG 512
#define LL 3
#define TG 64
#define NB ((NN + 1023) / 1024)   /* 98 scan blocks */
#define MTILES ((NN + 127) / 128) /* 782 */

#define PITCH 136                  /* floats; 136 % 32 == 8 -> conflict-free frag reads */
#define OPELEMS (FD * PITCH)       /* 17408 floats per operand */
#define SMEM_BYTES (2 * OPELEMS * 4) /* 139264 B */

// ---------------- device scratch (no allocs allowed) ----------------
__device__ float g_h[(size_t)NN * FD];
__device__ float g_aggr[(size_t)NN * FD];
__device__ float g_t[(size_t)NN * FD];
__device__ float g_wt[9 * FD * FD];     // pre-transposed weights [n][k]
__device__ int   g_deg[NN];
__device__ int   g_rowptr[NN + 1];
__device__ int   g_cursor[NN];
__device__ int   g_bsum[NB];
__device__ int   g_boff[NB];
__device__ int   g_srcsorted[EE];
__device__ int   g_gstart[GG + 1];

__device__ __forceinline__ uint32_t f2tf32(float f) {
    uint32_t r;
    asm("cvt.rna.tf32.f32 %0, %1;" : "=r"(r) : "f"(f));
    return r;
}

__device__ __forceinline__ void mma_tf32(float* c, const uint32_t* a, const uint32_t* b) {
    asm volatile(
        "mma.sync.aligned.m16n8k8.row.col.f32.tf32.tf32.f32 "
        "{%0,%1,%2,%3}, {%4,%5,%6,%7}, {%8,%9}, {%0,%1,%2,%3};"
        : "+f"(c[0]), "+f"(c[1]), "+f"(c[2]), "+f"(c[3])
        : "r"(a[0]), "r"(a[1]), "r"(a[2]), "r"(a[3]), "r"(b[0]), "r"(b[1]));
}

// ---------------- CSR build ----------------
__global__ void k_zero_deg() {
    int i = blockIdx.x * 256 + threadIdx.x;
    if (i < NN) g_deg[i] = 0;
}
__global__ void k_hist(const int* __restrict__ dst) {
    int e = blockIdx.x * 256 + threadIdx.x;
    if (e < EE) atomicAdd(&g_deg[dst[e]], 1);
}
__global__ void k_scan1() {
    __shared__ int sh[1024];
    int i = blockIdx.x * 1024 + threadIdx.x;
    int v = (i < NN) ? g_deg[i] : 0;
    sh[threadIdx.x] = v;
    __syncthreads();
    for (int off = 1; off < 1024; off <<= 1) {
        int t = sh[threadIdx.x];
        int a = (threadIdx.x >= off) ? sh[threadIdx.x - off] : 0;
        __syncthreads();
        sh[threadIdx.x] = t + a;
        __syncthreads();
    }
    if (i < NN) g_rowptr[i + 1] = sh[threadIdx.x];
    if (threadIdx.x == 1023) g_bsum[blockIdx.x] = sh[1023];
}
__global__ void k_scan2() {
    __shared__ int sh[128];
    int t = threadIdx.x;
    int v = (t < NB) ? g_bsum[t] : 0;
    sh[t] = v;
    __syncthreads();
    for (int off = 1; off < 128; off <<= 1) {
        int x = sh[t];
        int a = (t >= off) ? sh[t - off] : 0;
        __syncthreads();
        sh[t] = x + a;
        __syncthreads();
    }
    if (t < NB) g_boff[t] = sh[t] - v;
}
__global__ void k_scan3() {
    int i = blockIdx.x * 1024 + threadIdx.x;
    if (i < NN) g_rowptr[i + 1] += g_boff[blockIdx.x];
    if (i == 0) g_rowptr[0] = 0;
}
__global__ void k_copycur() {
    int i = blockIdx.x * 256 + threadIdx.x;
    if (i < NN) g_cursor[i] = g_rowptr[i];
}
__global__ void k_bucket(const int* __restrict__ src, const int* __restrict__ dst) {
    int e = blockIdx.x * 256 + threadIdx.x;
    if (e < EE) {
        int d = dst[e];
        int pos = atomicAdd(&g_cursor[d], 1);
        g_srcsorted[pos] = src[e];
    }
}
__global__ void k_gstart(const int* __restrict__ batch) {
    int g = blockIdx.x * 256 + threadIdx.x;
    if (g <= GG) {
        int lo = 0, hi = NN;
        while (lo < hi) {
            int mid = (lo + hi) >> 1;
            if (batch[mid] < g) lo = mid + 1; else hi = mid;
        }
        g_gstart[g] = lo;
    }
}

// ---------------- weight transpose: g_wt[mi][n][k] = W[mi][k][n] ----------------
__global__ void k_wtrans(const float* __restrict__ w1, const float* __restrict__ w2,
                         const float* __restrict__ w3) {
    __shared__ float t[32][33];
    int mi = blockIdx.z;
    const float* src = (mi < 3) ? (w1 + (size_t)mi * FD * FD)
                     : (mi < 6) ? (w2 + (size_t)(mi - 3) * FD * FD)
                                : (w3 + (size_t)(mi - 6) * FD * FD);
    float* dst = g_wt + (size_t)mi * FD * FD;
    int x0 = blockIdx.x * 32, y0 = blockIdx.y * 32;
    for (int dy = threadIdx.y; dy < 32; dy += 8)
        t[dy][threadIdx.x] = src[(size_t)(y0 + dy) * FD + x0 + threadIdx.x];
    __syncthreads();
    for (int dy = threadIdx.y; dy < 32; dy += 8)
        dst[(size_t)(x0 + dy) * FD + y0 + threadIdx.x] = t[threadIdx.x][dy];
}

// ---------------- aggregation: warp-per-node gather-sum ----------------
__global__ void __launch_bounds__(256) k_aggr(const float* __restrict__ h) {
    int node = blockIdx.x * 8 + (threadIdx.x >> 5);
    if (node >= NN) return;
    int lane = threadIdx.x & 31;
    int s = g_rowptr[node], e = g_rowptr[node + 1];
    const float4* hp = (const float4*)h;
    float4 acc = make_float4(0.f, 0.f, 0.f, 0.f);
    int i = s;
    for (; i + 1 < e; i += 2) {
        int s0 = g_srcsorted[i], s1 = g_srcsorted[i + 1];
        float4 v0 = hp[(size_t)s0 * 32 + lane];
        float4 v1 = hp[(size_t)s1 * 32 + lane];
        acc.x += v0.x + v1.x; acc.y += v0.y + v1.y;
        acc.z += v0.z + v1.z; acc.w += v0.w + v1.w;
    }
    if (i < e) {
        int s0 = g_srcsorted[i];
        float4 v0 = hp[(size_t)s0 * 32 + lane];
        acc.x += v0.x; acc.y += v0.y; acc.z += v0.z; acc.w += v0.w;
    }
    ((float4*)g_aggr)[(size_t)node * 32 + lane] = acc;
}

// ---------------- tf32 mma.sync GEMM: C[M,128] = act(pre(A) @ Wt^T + bias) ----------------
// Wt is [n][k] row-major. pre(A) = (1+eps)*A + A1 when A1 != null.
// SMEM: As/Bs in [k][m]-major tf32 bits, pitch 136 floats (conflict-free frag LDS).
__global__ void __launch_bounds__(256) k_gemm_mma(
    const float* __restrict__ A, const float* __restrict__ A1,
    const float* __restrict__ epsp,
    const float* __restrict__ Wt, const float* __restrict__ bias,
    float* __restrict__ C, int M, int relu)
{
    extern __shared__ uint32_t smem[];
    uint32_t* As = smem;            // [k=128][m=128] pitch PITCH
    uint32_t* Bs = smem + OPELEMS;  // [k=128][n=128] pitch PITCH

    int tid = threadIdx.x;
    int w = tid >> 5, lane = tid & 31;
    int m0 = blockIdx.x * 128;
    float alpha = epsp ? (1.0f + epsp[0]) : 1.0f;

    // ---- stage tiles: per warp-iter tile = 16 rows x 2 float4 (8 k) ----
    // wt = i*8 + w in 0..127: mb = wt & 7 (16-row block), qb = wt >> 3 (0..15, 2-quad block)
    {
        int g2 = lane >> 1;         // 0..15 row within block
        int t2 = lane & 1;          // 0..1 quad within block
#pragma unroll
        for (int i = 0; i < 16; i++) {
            int wt = i * 8 + w;
            int mb = wt & 7, qb = wt >> 3;
            int row = mb * 16 + g2;             // 0..127
            int q = qb * 2 + t2;                // float4 index 0..31
            int k = q * 4;
            // A side (+ GIN combine)
            int m = m0 + row;
            float4 v = make_float4(0.f, 0.f, 0.f, 0.f);
            if (m < M) {
                v = *(const float4*)&A[(size_t)m * FD + k];
                if (A1) {
                    float4 u = *(const float4*)&A1[(size_t)m * FD + k];
                    v.x = alpha * v.x + u.x; v.y = alpha * v.y + u.y;
                    v.z = alpha * v.z + u.z; v.w = alpha * v.w + u.w;
                }
            }
            As[(k + 0) * PITCH + row] = f2tf32(v.x);
            As[(k + 1) * PITCH + row] = f2tf32(v.y);
            As[(k + 2) * PITCH + row] = f2tf32(v.z);
            As[(k + 3) * PITCH + row] = f2tf32(v.w);
            // B side: Wt row = n
            float4 b = *(const float4*)&Wt[(size_t)row * FD + k];
            Bs[(k + 0) * PITCH + row] = f2tf32(b.x);
            Bs[(k + 1) * PITCH + row] = f2tf32(b.y);
            Bs[(k + 2) * PITCH + row] = f2tf32(b.z);
            Bs[(k + 3) * PITCH + row] = f2tf32(b.w);
        }
    }
    __syncthreads();

    // ---- compute: warp grid 2(m) x 4(n); warp tile 64 x 32 ----
    int warpM = w >> 2, warpN = w & 3;
    int g = lane >> 2, t = lane & 3;
    int rbase = warpM * 64 + g;         // + ma*16 (+8 for a1/a3)
    int cbase = warpN * 32 + g;         // + nb*8

    float c[4][4][4];
#pragma unroll
    for (int ma = 0; ma < 4; ma++)
#pragma unroll
        for (int nb = 0; nb < 4; nb++)
#pragma unroll
            for (int r = 0; r < 4; r++) c[ma][nb][r] = 0.f;

#pragma unroll
    for (int ks = 0; ks < 16; ks++) {
        int k0 = ks * 8;
        const uint32_t* a_lo = As + (k0 + t) * PITCH;
        const uint32_t* a_hi = As + (k0 + t + 4) * PITCH;
        uint32_t af[4][4];
#pragma unroll
        for (int ma = 0; ma < 4; ma++) {
            int r = rbase + ma * 16;
            af[ma][0] = a_lo[r];
            af[ma][1] = a_lo[r + 8];
            af[ma][2] = a_hi[r];
            af[ma][3] = a_hi[r + 8];
        }
        const uint32_t* b_lo = Bs + (k0 + t) * PITCH;
        const uint32_t* b_hi = Bs + (k0 + t + 4) * PITCH;
        uint32_t bf[4][2];
#pragma unroll
        for (int nb = 0; nb < 4; nb++) {
            int cn = cbase + nb * 8;
            bf[nb][0] = b_lo[cn];
            bf[nb][1] = b_hi[cn];
        }
#pragma unroll
        for (int ma = 0; ma < 4; ma++)
#pragma unroll
            for (int nb = 0; nb < 4; nb++)
                mma_tf32(c[ma][nb], af[ma], bf[nb]);
    }

    // ---- epilogue: bias + optional relu ----
#pragma unroll
    for (int ma = 0; ma < 4; ma++) {
        int r0 = m0 + warpM * 64 + ma * 16 + g;
#pragma unroll
        for (int nb = 0; nb < 4; nb++) {
            int cn = warpN * 32 + nb * 8 + 2 * t;
            float b0 = bias[cn], b1 = bias[cn + 1];
            float o0 = c[ma][nb][0] + b0, o1 = c[ma][nb][1] + b1;
            float o2 = c[ma][nb][2] + b0, o3 = c[ma][nb][3] + b1;
            if (relu) {
                o0 = fmaxf(o0, 0.f); o1 = fmaxf(o1, 0.f);
                o2 = fmaxf(o2, 0.f); o3 = fmaxf(o3, 0.f);
            }
            if (r0 < M)     *(float2*)&C[(size_t)r0 * FD + cn]       = make_float2(o0, o1);
            if (r0 + 8 < M) *(float2*)&C[(size_t)(r0 + 8) * FD + cn] = make_float2(o2, o3);
        }
    }
}

// ---------------- GraphNorm (+relu) in place ----------------
__global__ void __launch_bounds__(128) k_gnorm(
    float* __restrict__ h,
    const float* __restrict__ scale, const float* __restrict__ weight,
    const float* __restrict__ bias)
{
    int g = blockIdx.x;
    int f = threadIdx.x;
    int s = g_gstart[g], e = g_gstart[g + 1];
    float cnt = fmaxf((float)(e - s), 1.0f);

    float sum = 0.f;
#pragma unroll 4
    for (int i = s; i < e; i++) sum += h[(size_t)i * FD + f];
    float ms = (sum / cnt) * scale[f];

    float v = 0.f;
#pragma unroll 4
    for (int i = s; i < e; i++) {
        float d = h[(size_t)i * FD + f] - ms;
        v += d * d;
    }
    float inv = weight[f] * rsqrtf(v / cnt + 1e-8f);
    float bf = bias[f];

#pragma unroll 4
    for (int i = s; i < e; i++) {
        float d = h[(size_t)i * FD + f] - ms;
        h[(size_t)i * FD + f] = fmaxf(inv * d + bf, 0.f);
    }
}

// ---------------- pool + fused tiny GEMM ----------------
__global__ void __launch_bounds__(128) k_pool(
    const float* __restrict__ t,
    const float* __restrict__ w2, const float* __restrict__ b2,
    float* __restrict__ out, int lofs)
{
    __shared__ float sp[128];
    int g = blockIdx.x;
    int f = threadIdx.x;
    int s = g_gstart[g], e = g_gstart[g + 1];
    float acc = 0.f;
#pragma unroll 4
    for (int i = s; i < e; i++) acc += t[(size_t)i * FD + f];
    sp[f] = acc;
    __syncthreads();
    if (f < TG) {
        float o = (float)(e - s) * b2[f];
#pragma unroll 8
        for (int k = 0; k < FD; k++) o += sp[k] * w2[k * TG + f];
        out[(size_t)g * (LL * TG) + lofs + f] = o;
    }
}

// ---------------- launcher ----------------
extern "C" void kernel_launch(void* const* d_in, const int* in_sizes, int n_in,
                              void* d_out, int out_size) {
    const float* x        = (const float*)d_in[0];
    const int*   edge     = (const int*)d_in[1];
    const int*   batch    = (const int*)d_in[2];
    const float* conv_w1  = (const float*)d_in[3];
    const float* conv_b1  = (const float*)d_in[4];
    const float* conv_w2  = (const float*)d_in[5];
    const float* conv_b2  = (const float*)d_in[6];
    const float* eps      = (const float*)d_in[7];
    const float* gn_scale = (const float*)d_in[8];
    const float* gn_weight= (const float*)d_in[9];
    const float* gn_bias  = (const float*)d_in[10];
    const float* proj_w1  = (const float*)d_in[11];
    const float* proj_b1  = (const float*)d_in[12];
    const float* proj_w2  = (const float*)d_in[13];
    const float* proj_b2  = (const float*)d_in[14];
    float* out = (float*)d_out;

    const int* src = edge;
    const int* dst = edge + EE;

    float *p_h, *p_aggr, *p_t, *p_wt;
    cudaGetSymbolAddress((void**)&p_h, g_h);
    cudaGetSymbolAddress((void**)&p_aggr, g_aggr);
    cudaGetSymbolAddress((void**)&p_t, g_t);
    cudaGetSymbolAddress((void**)&p_wt, g_wt);

    cudaFuncSetAttribute(k_gemm_mma, cudaFuncAttributeMaxDynamicSharedMemorySize, SMEM_BYTES);

    // CSR build + graph starts + weight transpose
    k_zero_deg<<<(NN + 255) / 256, 256>>>();
    k_hist<<<(EE + 255) / 256, 256>>>(dst);
    k_scan1<<<NB, 1024>>>();
    k_scan2<<<1, 128>>>();
    k_scan3<<<NB, 1024>>>();
    k_copycur<<<(NN + 255) / 256, 256>>>();
    k_bucket<<<(EE + 255) / 256, 256>>>(src, dst);
    k_gstart<<<3, 256>>>(batch);
    k_wtrans<<<dim3(4, 4, 9), dim3(32, 8)>>>(conv_w1, conv_w2, proj_w1);

    const float* h = x;
    for (int l = 0; l < LL; l++) {
        k_aggr<<<(NN + 7) / 8, 256>>>(h);
        // t = relu(((1+eps)h + aggr) @ conv_w1 + b1)
        k_gemm_mma<<<MTILES, 256, SMEM_BYTES>>>(h, p_aggr, eps + l,
                                                p_wt + (size_t)l * FD * FD,
                                                conv_b1 + (size_t)l * FD, p_t, NN, 1);
        // h = t @ conv_w2 + b2
        k_gemm_mma<<<MTILES, 256, SMEM_BYTES>>>(p_t, nullptr, nullptr,
                                                p_wt + (size_t)(3 + l) * FD * FD,
                                                conv_b2 + (size_t)l * FD, p_h, NN, 0);
        // GraphNorm + relu
        k_gnorm<<<GG, 128>>>(p_h, gn_scale + (size_t)l * FD,
                             gn_weight + (size_t)l * FD, gn_bias + (size_t)l * FD);
        // t = relu(h @ proj_w1 + b1)
        k_gemm_mma<<<MTILES, 256, SMEM_BYTES>>>(p_h, nullptr, nullptr,
                                                p_wt + (size_t)(6 + l) * FD * FD,
                                                proj_b1 + (size_t)l * FD, p_t, NN, 1);
        // pooled projection
        k_pool<<<GG, 128>>>(p_t, proj_w2 + (size_t)l * FD * TG,
                            proj_b2 + (size_t)l * TG, out, l * TG);
        h = p_h;
    }
}

// round 4
// speedup vs baseline: 1.7105x; 1.2660x over previous
#include <cuda_runtime.h>
#include <cstdint>

#define NN 100000
#define EE 1600000
#define FD 128
#define GG 512
#define LL 3
#define TG 64
#define NB ((NN + 1023) / 1024)   /* 98 scan blocks */
#define MTILES ((NN + 127) / 128) /* 782 */

#define BK 32                      /* K-chunk */
#define PIT 36                     /* floats per row: bank(m,k) = (4m+k)%32, conflict-free frags */
#define ABUF (128 * PIT)           /* 4608 floats: A chunk */
#define BUFSZ (2 * ABUF)           /* A + B per buffer = 9216 floats */
#define SMEM_BYTES (2 * BUFSZ * 4) /* 73728 B double-buffered */

// ---------------- device scratch (no allocs allowed) ----------------
__device__ float g_h[(size_t)NN * FD];
__device__ float g_aggr[(size_t)NN * FD];
__device__ float g_t[(size_t)NN * FD];
__device__ float g_wt[9 * FD * FD];     // pre-transposed weights [n][k]
__device__ int   g_deg[NN];
__device__ int   g_rowptr[NN + 1];
__device__ int   g_cursor[NN];
__device__ int   g_bsum[NB];
__device__ int   g_boff[NB];
__device__ int   g_srcsorted[EE];
__device__ int   g_gstart[GG + 1];

__device__ __forceinline__ uint32_t smem_u32(const void* p) {
    uint32_t a;
    asm("{ .reg .u64 t; cvta.to.shared.u64 t, %1; cvt.u32.u64 %0, t; }" : "=r"(a) : "l"(p));
    return a;
}
__device__ __forceinline__ void cp16(uint32_t dst, const void* src, int sz) {
    asm volatile("cp.async.cg.shared.global [%0], [%1], 16, %2;"
                 :: "r"(dst), "l"(src), "r"(sz) : "memory");
}
__device__ __forceinline__ void mma_tf32(float* c, const uint32_t* a, const uint32_t* b) {
    asm volatile(
        "mma.sync.aligned.m16n8k8.row.col.f32.tf32.tf32.f32 "
        "{%0,%1,%2,%3}, {%4,%5,%6,%7}, {%8,%9}, {%0,%1,%2,%3};"
        : "+f"(c[0]), "+f"(c[1]), "+f"(c[2]), "+f"(c[3])
        : "r"(a[0]), "r"(a[1]), "r"(a[2]), "r"(a[3]), "r"(b[0]), "r"(b[1]));
}

// ---------------- CSR build ----------------
__global__ void k_zero_deg() {
    int i = blockIdx.x * 256 + threadIdx.x;
    if (i < NN) g_deg[i] = 0;
}
__global__ void k_hist(const int* __restrict__ dst) {
    int e = blockIdx.x * 256 + threadIdx.x;
    if (e < EE) atomicAdd(&g_deg[dst[e]], 1);
}
__global__ void k_scan1() {
    __shared__ int sh[1024];
    int i = blockIdx.x * 1024 + threadIdx.x;
    int v = (i < NN) ? g_deg[i] : 0;
    sh[threadIdx.x] = v;
    __syncthreads();
    for (int off = 1; off < 1024; off <<= 1) {
        int t = sh[threadIdx.x];
        int a = (threadIdx.x >= off) ? sh[threadIdx.x - off] : 0;
        __syncthreads();
        sh[threadIdx.x] = t + a;
        __syncthreads();
    }
    if (i < NN) g_rowptr[i + 1] = sh[threadIdx.x];
    if (threadIdx.x == 1023) g_bsum[blockIdx.x] = sh[1023];
}
__global__ void k_scan2() {
    __shared__ int sh[128];
    int t = threadIdx.x;
    int v = (t < NB) ? g_bsum[t] : 0;
    sh[t] = v;
    __syncthreads();
    for (int off = 1; off < 128; off <<= 1) {
        int x = sh[t];
        int a = (t >= off) ? sh[t - off] : 0;
        __syncthreads();
        sh[t] = x + a;
        __syncthreads();
    }
    if (t < NB) g_boff[t] = sh[t] - v;
}
__global__ void k_scan3() {
    int i = blockIdx.x * 1024 + threadIdx.x;
    if (i < NN) g_rowptr[i + 1] += g_boff[blockIdx.x];
    if (i == 0) g_rowptr[0] = 0;
}
__global__ void k_copycur() {
    int i = blockIdx.x * 256 + threadIdx.x;
    if (i < NN) g_cursor[i] = g_rowptr[i];
}
__global__ void k_bucket(const int* __restrict__ src, const int* __restrict__ dst) {
    int e = blockIdx.x * 256 + threadIdx.x;
    if (e < EE) {
        int d = dst[e];
        int pos = atomicAdd(&g_cursor[d], 1);
        g_srcsorted[pos] = src[e];
    }
}
__global__ void k_gstart(const int* __restrict__ batch) {
    int g = blockIdx.x * 256 + threadIdx.x;
    if (g <= GG) {
        int lo = 0, hi = NN;
        while (lo < hi) {
            int mid = (lo + hi) >> 1;
            if (batch[mid] < g) lo = mid + 1; else hi = mid;
        }
        g_gstart[g] = lo;
    }
}

// ---------------- weight transpose: g_wt[mi][n][k] = W[mi][k][n] ----------------
__global__ void k_wtrans(const float* __restrict__ w1, const float* __restrict__ w2,
                         const float* __restrict__ w3) {
    __shared__ float t[32][33];
    int mi = blockIdx.z;
    const float* src = (mi < 3) ? (w1 + (size_t)mi * FD * FD)
                     : (mi < 6) ? (w2 + (size_t)(mi - 3) * FD * FD)
                                : (w3 + (size_t)(mi - 6) * FD * FD);
    float* dst = g_wt + (size_t)mi * FD * FD;
    int x0 = blockIdx.x * 32, y0 = blockIdx.y * 32;
    for (int dy = threadIdx.y; dy < 32; dy += 8)
        t[dy][threadIdx.x] = src[(size_t)(y0 + dy) * FD + x0 + threadIdx.x];
    __syncthreads();
    for (int dy = threadIdx.y; dy < 32; dy += 8)
        dst[(size_t)(x0 + dy) * FD + y0 + threadIdx.x] = t[threadIdx.x][dy];
}

// ---------------- aggregation + GIN combine: aggr = (1+eps)*h[node] + sum_{src} h[src] ----------------
__global__ void __launch_bounds__(256) k_aggr(const float* __restrict__ h,
                                              const float* __restrict__ epsp) {
    int node = blockIdx.x * 8 + (threadIdx.x >> 5);
    if (node >= NN) return;
    int lane = threadIdx.x & 31;
    int s = g_rowptr[node], e = g_rowptr[node + 1];
    float alpha = 1.0f + epsp[0];
    const float4* hp = (const float4*)h;
    float4 hv = hp[(size_t)node * 32 + lane];
    float4 acc = make_float4(alpha * hv.x, alpha * hv.y, alpha * hv.z, alpha * hv.w);
    int i = s;
    for (; i + 1 < e; i += 2) {
        int s0 = g_srcsorted[i], s1 = g_srcsorted[i + 1];
        float4 v0 = hp[(size_t)s0 * 32 + lane];
        float4 v1 = hp[(size_t)s1 * 32 + lane];
        acc.x += v0.x + v1.x; acc.y += v0.y + v1.y;
        acc.z += v0.z + v1.z; acc.w += v0.w + v1.w;
    }
    if (i < e) {
        int s0 = g_srcsorted[i];
        float4 v0 = hp[(size_t)s0 * 32 + lane];
        acc.x += v0.x; acc.y += v0.y; acc.z += v0.z; acc.w += v0.w;
    }
    ((float4*)g_aggr)[(size_t)node * 32 + lane] = acc;
}

// ---------------- tf32 mma GEMM, cp.async double-buffered K-chunks ----------------
// C[M,128] = act(A @ Wt^T + bias); Wt is [n][k] row-major.
// SMEM per buffer: A [128m][PIT] + B [128n][PIT] (raw fp32 bits; HMMA truncates to tf32).
__global__ void __launch_bounds__(256) k_gemm_cp(
    const float* __restrict__ A,
    const float* __restrict__ Wt, const float* __restrict__ bias,
    float* __restrict__ C, int M, int relu)
{
    extern __shared__ float smem[];
    uint32_t sb = smem_u32(smem);

    int tid = threadIdx.x;
    int w = tid >> 5, lane = tid & 31;
    int m0 = blockIdx.x * 128;

    // staging map: 2048 x 16B per chunk; thread does 8 (i*256 + tid)
    // o < 1024 -> A side, else B; row = (o & 1023) >> 3; q = o & 7
    auto stage = [&](int c, int buf) {
        uint32_t base = sb + (uint32_t)buf * (BUFSZ * 4);
#pragma unroll
        for (int i = 0; i < 8; i++) {
            int o = i * 256 + tid;
            int row = (o & 1023) >> 3;
            int q = o & 7;
            uint32_t dst = base + (uint32_t)((o >> 10) * (ABUF * 4) + row * (PIT * 4) + q * 16);
            if (o < 1024) {
                int m = m0 + row;
                const float* src = A + ((m < M) ? ((size_t)m * FD + c * BK + q * 4) : 0);
                cp16(dst, src, (m < M) ? 16 : 0);
            } else {
                cp16(dst, Wt + (size_t)row * FD + c * BK + q * 4, 16);
            }
        }
        asm volatile("cp.async.commit_group;" ::: "memory");
    };

    stage(0, 0);

    int warpM = w >> 2, warpN = w & 3;
    int g = lane >> 2, t = lane & 3;

    float c[4][4][4];
#pragma unroll
    for (int ma = 0; ma < 4; ma++)
#pragma unroll
        for (int nb = 0; nb < 4; nb++)
#pragma unroll
            for (int r = 0; r < 4; r++) c[ma][nb][r] = 0.f;

#pragma unroll
    for (int ch = 0; ch < 4; ch++) {
        if (ch < 3) stage(ch + 1, (ch + 1) & 1);
        if (ch < 3)
            asm volatile("cp.async.wait_group 1;" ::: "memory");
        else
            asm volatile("cp.async.wait_group 0;" ::: "memory");
        __syncthreads();

        const uint32_t* As = (const uint32_t*)(smem + (ch & 1) * BUFSZ);
        const uint32_t* Bs = As + ABUF;

#pragma unroll
        for (int ks = 0; ks < 4; ks++) {
            int k0 = ks * 8;
            uint32_t af[4][4];
#pragma unroll
            for (int ma = 0; ma < 4; ma++) {
                int r = warpM * 64 + ma * 16 + g;
                const uint32_t* ap = As + r * PIT + k0 + t;
                af[ma][0] = ap[0];
                af[ma][1] = ap[8 * PIT];
                af[ma][2] = ap[4];
                af[ma][3] = ap[8 * PIT + 4];
            }
            uint32_t bf[4][2];
#pragma unroll
            for (int nb = 0; nb < 4; nb++) {
                int n = warpN * 32 + nb * 8 + g;
                const uint32_t* bp = Bs + n * PIT + k0 + t;
                bf[nb][0] = bp[0];
                bf[nb][1] = bp[4];
            }
#pragma unroll
            for (int ma = 0; ma < 4; ma++)
#pragma unroll
                for (int nb = 0; nb < 4; nb++)
                    mma_tf32(c[ma][nb], af[ma], bf[nb]);
        }
        __syncthreads();
    }

    // ---- epilogue: bias + optional relu ----
#pragma unroll
    for (int ma = 0; ma < 4; ma++) {
        int r0 = m0 + warpM * 64 + ma * 16 + g;
#pragma unroll
        for (int nb = 0; nb < 4; nb++) {
            int cn = warpN * 32 + nb * 8 + 2 * t;
            float b0 = bias[cn], b1 = bias[cn + 1];
            float o0 = c[ma][nb][0] + b0, o1 = c[ma][nb][1] + b1;
            float o2 = c[ma][nb][2] + b0, o3 = c[ma][nb][3] + b1;
            if (relu) {
                o0 = fmaxf(o0, 0.f); o1 = fmaxf(o1, 0.f);
                o2 = fmaxf(o2, 0.f); o3 = fmaxf(o3, 0.f);
            }
            if (r0 < M)     *(float2*)&C[(size_t)r0 * FD + cn]       = make_float2(o0, o1);
            if (r0 + 8 < M) *(float2*)&C[(size_t)(r0 + 8) * FD + cn] = make_float2(o2, o3);
        }
    }
}

// ---------------- GraphNorm (+relu) in place ----------------
__global__ void __launch_bounds__(128) k_gnorm(
    float* __restrict__ h,
    const float* __restrict__ scale, const float* __restrict__ weight,
    const float* __restrict__ bias)
{
    int g = blockIdx.x;
    int f = threadIdx.x;
    int s = g_gstart[g], e = g_gstart[g + 1];
    float cnt = fmaxf((float)(e - s), 1.0f);

    float sum = 0.f;
#pragma unroll 4
    for (int i = s; i < e; i++) sum += h[(size_t)i * FD + f];
    float ms = (sum / cnt) * scale[f];

    float v = 0.f;
#pragma unroll 4
    for (int i = s; i < e; i++) {
        float d = h[(size_t)i * FD + f] - ms;
        v += d * d;
    }
    float inv = weight[f] * rsqrtf(v / cnt + 1e-8f);
    float bf = bias[f];

#pragma unroll 4
    for (int i = s; i < e; i++) {
        float d = h[(size_t)i * FD + f] - ms;
        h[(size_t)i * FD + f] = fmaxf(inv * d + bf, 0.f);
    }
}

// ---------------- pool + fused tiny GEMM ----------------
__global__ void __launch_bounds__(128) k_pool(
    const float* __restrict__ t,
    const float* __restrict__ w2, const float* __restrict__ b2,
    float* __restrict__ out, int lofs)
{
    __shared__ float sp[128];
    int g = blockIdx.x;
    int f = threadIdx.x;
    int s = g_gstart[g], e = g_gstart[g + 1];
    float acc = 0.f;
#pragma unroll 4
    for (int i = s; i < e; i++) acc += t[(size_t)i * FD + f];
    sp[f] = acc;
    __syncthreads();
    if (f < TG) {
        float o = (float)(e - s) * b2[f];
#pragma unroll 8
        for (int k = 0; k < FD; k++) o += sp[k] * w2[k * TG + f];
        out[(size_t)g * (LL * TG) + lofs + f] = o;
    }
}

// ---------------- launcher ----------------
extern "C" void kernel_launch(void* const* d_in, const int* in_sizes, int n_in,
                              void* d_out, int out_size) {
    const float* x        = (const float*)d_in[0];
    const int*   edge     = (const int*)d_in[1];
    const int*   batch    = (const int*)d_in[2];
    const float* conv_w1  = (const float*)d_in[3];
    const float* conv_b1  = (const float*)d_in[4];
    const float* conv_w2  = (const float*)d_in[5];
    const float* conv_b2  = (const float*)d_in[6];
    const float* eps      = (const float*)d_in[7];
    const float* gn_scale = (const float*)d_in[8];
    const float* gn_weight= (const float*)d_in[9];
    const float* gn_bias  = (const float*)d_in[10];
    const float* proj_w1  = (const float*)d_in[11];
    const float* proj_b1  = (const float*)d_in[12];
    const float* proj_w2  = (const float*)d_in[13];
    const float* proj_b2  = (const float*)d_in[14];
    float* out = (float*)d_out;

    const int* src = edge;
    const int* dst = edge + EE;

    float *p_h, *p_aggr, *p_t, *p_wt;
    cudaGetSymbolAddress((void**)&p_h, g_h);
    cudaGetSymbolAddress((void**)&p_aggr, g_aggr);
    cudaGetSymbolAddress((void**)&p_t, g_t);
    cudaGetSymbolAddress((void**)&p_wt, g_wt);

    cudaFuncSetAttribute(k_gemm_cp, cudaFuncAttributeMaxDynamicSharedMemorySize, SMEM_BYTES);

    // CSR build + graph starts + weight transpose
    k_zero_deg<<<(NN + 255) / 256, 256>>>();
    k_hist<<<(EE + 255) / 256, 256>>>(dst);
    k_scan1<<<NB, 1024>>>();
    k_scan2<<<1, 128>>>();
    k_scan3<<<NB, 1024>>>();
    k_copycur<<<(NN + 255) / 256, 256>>>();
    k_bucket<<<(EE + 255) / 256, 256>>>(src, dst);
    k_gstart<<<3, 256>>>(batch);
    k_wtrans<<<dim3(4, 4, 9), dim3(32, 8)>>>(conv_w1, conv_w2, proj_w1);

    const float* h = x;
    for (int l = 0; l < LL; l++) {
        // aggr = (1+eps)h + sum_{j in N(i)} h_j
        k_aggr<<<(NN + 7) / 8, 256>>>(h, eps + l);
        // t = relu(aggr @ conv_w1 + b1)
        k_gemm_cp<<<MTILES, 256, SMEM_BYTES>>>(p_aggr,
                                               p_wt + (size_t)l * FD * FD,
                                               conv_b1 + (size_t)l * FD, p_t, NN, 1);
        // h = t @ conv_w2 + b2
        k_gemm_cp<<<MTILES, 256, SMEM_BYTES>>>(p_t,
                                               p_wt + (size_t)(3 + l) * FD * FD,
                                               conv_b2 + (size_t)l * FD, p_h, NN, 0);
        // GraphNorm + relu
        k_gnorm<<<GG, 128>>>(p_h, gn_scale + (size_t)l * FD,
                             gn_weight + (size_t)l * FD, gn_bias + (size_t)l * FD);
        // t = relu(h @ proj_w1 + b1)
        k_gemm_cp<<<MTILES, 256, SMEM_BYTES>>>(p_h,
                                               p_wt + (size_t)(6 + l) * FD * FD,
                                               proj_b1 + (size_t)l * FD, p_t, NN, 1);
        // pooled projection
        k_pool<<<GG, 128>>>(p_t, proj_w2 + (size_t)l * FD * TG,
                            proj_b2 + (size_t)l * TG, out, l * TG);
        h = p_h;
    }
}